// round 15
// baseline (speedup 1.0000x reference)
#include <cuda_runtime.h>
#include <cstdint>

#define L 32768
#define H 256
#define P 256
#define KS 36            // gemm1 A smem row stride (floats)
#define AS2B 528         // gemm2 A smem per-p stride (floats), 512 + 16 pad

// Scratch (device globals; allocation is forbidden)
__device__ __align__(16) float2 g_bu[(size_t)P * L];      // Bu then xs, (P, L)
__device__ __align__(16) float g_BpF[8 * 8 * 2048];       // B'  frag-order [nt64][kc][2048]
__device__ __align__(16) float g_CpF[4 * 16 * 2048];      // C'  frag-order [nt64][kc][2048]
__device__ float2 g_lam[P];
__device__ float2 g_coef[P];

__device__ __forceinline__ float2 cmul(float2 a, float2 b) {
    return make_float2(a.x * b.x - a.y * b.y, a.x * b.y + a.y * b.x);
}
__device__ __forceinline__ float tf32r(float f) {
    unsigned u;
    asm("cvt.rna.tf32.f32 %0, %1;" : "=r"(u) : "f"(f));
    return __uint_as_float(u);
}
__device__ __forceinline__ void mma_tf32(float* c, const unsigned* a, unsigned b0, unsigned b1) {
    asm volatile(
        "mma.sync.aligned.m16n8k8.row.col.f32.tf32.tf32.f32 "
        "{%0,%1,%2,%3}, {%4,%5,%6,%7}, {%8,%9}, {%0,%1,%2,%3};"
        : "+f"(c[0]), "+f"(c[1]), "+f"(c[2]), "+f"(c[3])
        : "r"(a[0]), "r"(a[1]), "r"(a[2]), "r"(a[3]), "r"(b0), "r"(b1));
}
__device__ __forceinline__ void cp16(uint32_t dst, const void* src) {
    asm volatile("cp.async.cg.shared.global [%0], [%1], 16;" :: "r"(dst), "l"(src));
}
__device__ __forceinline__ void cp_commit() { asm volatile("cp.async.commit_group;"); }
template<int N> __device__ __forceinline__ void cp_wait() {
    asm volatile("cp.async.wait_group %0;" :: "n"(N));
}

// ---------------------------------------------------------------------------
// ZOH discretization
// ---------------------------------------------------------------------------
__global__ void precompute_kernel(const float* __restrict__ Lambda_ri,
                                  const float* __restrict__ log_step) {
    int p = threadIdx.x;
    float lr = Lambda_ri[2 * p], li = Lambda_ri[2 * p + 1];
    float dt = expf(log_step[p]);
    float mag = expf(lr * dt);
    float s, c;
    sincosf(li * dt, &s, &c);
    float2 lam = make_float2(mag * c, mag * s);
    float2 num = make_float2(lam.x - 1.0f, lam.y);
    float inv = 1.0f / (lr * lr + li * li);
    g_lam[p] = lam;
    g_coef[p] = make_float2((num.x * lr + num.y * li) * inv,
                            (num.y * lr - num.x * li) * inv);
}

// Fragment-order offset within a 64x32 (N x K) chunk image (2048 floats)
__device__ __forceinline__ int frag_off(int nr, int kr) {
    return (((nr >> 4) * 4 + (kr >> 3)) << 7) +
           (((nr & 7) * 4 + (kr & 3)) << 2) +
           ((nr >> 3) & 1) * 2 + ((kr >> 2) & 1);
}

// B' (K=256 rows h, N=512 cols 2p+c) -> 64-wide frag-order images
__global__ void pack_B_kernel(const float* __restrict__ B_ri) {
    int i = blockIdx.x * 256 + threadIdx.x;   // i < P*H
    int p = i >> 8, h = i & 255;
    float re = B_ri[(size_t)i * 2 + 0];
    float im = B_ri[(size_t)i * 2 + 1];
    #pragma unroll
    for (int c = 0; c < 2; c++) {
        int n = 2 * p + c, k = h;
        float v = tf32r(c ? im : re);
        g_BpF[((n >> 6) * 8 + (k >> 5)) * 2048 + frag_off(n & 63, k & 31)] = v;
    }
}

// C' (K=512 rows 2p+c, N=256 cols h): C'[2p]=Cre, C'[2p+1]=-Cim
__global__ void pack_C_kernel(const float* __restrict__ C_ri) {
    int i = blockIdx.x * 256 + threadIdx.x;   // i < H*P
    int h = i >> 8, p = i & 255;
    float re = C_ri[(size_t)i * 2 + 0];
    float im = C_ri[(size_t)i * 2 + 1];
    #pragma unroll
    for (int c = 0; c < 2; c++) {
        int n = h, k = 2 * p + c;
        float v = tf32r(c ? -im : re);
        g_CpF[((n >> 6) * 16 + (k >> 5)) * 2048 + frag_off(n & 63, k & 31)] = v;
    }
}

// ---------------------------------------------------------------------------
// GEMM1: Bu = sig (Lx256) @ B' (256x512); epilogue complex*coef, (P,L) writes.
// 256x64 CTA tile, 8 warps (4x2, 64x32 each), 2-stage ring, 2 CTAs/SM.
// ---------------------------------------------------------------------------
#define G1_AB (256 * KS)     // 9216 floats per A stage
#define G1_BB 2048
#define G1_STG (G1_AB + G1_BB)
__global__ __launch_bounds__(256, 2) void gemm1_kernel(const float* __restrict__ sig) {
    extern __shared__ float smem[];
    uint32_t base_u = (uint32_t)__cvta_generic_to_shared(smem);

    int tid = threadIdx.x, lane = tid & 31, wid = tid >> 5;
    int warp_m = wid & 3, warp_n = wid >> 2;        // 4 x 2, warp tile 64x32
    int quad = lane >> 2, tq = lane & 3;
    int nt = blockIdx.x;                             // 64-col n tile (0..7)
    int l0 = blockIdx.y * 256;

    float acc[4][4][4];
    #pragma unroll
    for (int mi = 0; mi < 4; mi++)
        #pragma unroll
        for (int nj = 0; nj < 4; nj++)
            #pragma unroll
            for (int q = 0; q < 4; q++) acc[mi][nj][q] = 0.f;

    auto load_chunk = [&](int kc, int sel) {
        uint32_t sA = base_u + sel * (G1_STG * 4);
        uint32_t sB = sA + G1_AB * 4;
        int k0 = kc * 32;
        #pragma unroll
        for (int i = tid; i < 2048; i += 256) {      // A: 256 rows x 8 segs (32 KB)
            int row = i >> 3, seg = i & 7;
            cp16(sA + (row * KS + seg * 4) * 4,
                 sig + (size_t)(l0 + row) * H + k0 + seg * 4);
        }
        const float* src = g_BpF + ((size_t)(nt * 8 + kc)) * 2048;
        #pragma unroll
        for (int i = tid; i < 512; i += 256)         // B: 2048 floats
            cp16(sB + i * 16, src + i * 4);
    };

    load_chunk(0, 0); cp_commit();
    load_chunk(1, 1); cp_commit();

    for (int kc = 0; kc < 8; kc++) {
        cp_wait<1>();
        __syncthreads();
        const float* sA = smem + (kc & 1) * G1_STG;
        const float* sB = sA + G1_AB;
        #pragma unroll
        for (int k8 = 0; k8 < 4; k8++) {
            int kb = k8 * 8;
            unsigned a[4][4];
            #pragma unroll
            for (int mi = 0; mi < 4; mi++) {
                int r = warp_m * 64 + mi * 16 + quad;
                a[mi][0] = __float_as_uint(sA[r * KS + kb + tq]);
                a[mi][1] = __float_as_uint(sA[(r + 8) * KS + kb + tq]);
                a[mi][2] = __float_as_uint(sA[r * KS + kb + tq + 4]);
                a[mi][3] = __float_as_uint(sA[(r + 8) * KS + kb + tq + 4]);
            }
            #pragma unroll
            for (int j = 0; j < 2; j++) {
                float4 bq = *(const float4*)(sB + (((warp_n * 2 + j) * 4 + k8) << 7) + lane * 4);
                #pragma unroll
                for (int mi = 0; mi < 4; mi++) {
                    mma_tf32(acc[mi][2 * j],     a[mi], __float_as_uint(bq.x), __float_as_uint(bq.y));
                    mma_tf32(acc[mi][2 * j + 1], a[mi], __float_as_uint(bq.z), __float_as_uint(bq.w));
                }
            }
        }
        __syncthreads();
        if (kc + 2 < 8) load_chunk(kc + 2, kc & 1);
        cp_commit();
    }

    // Epilogue: complex coef, transpose through smem, coalesced (P,L) stores
    int p0 = nt * 32;
    float2* bufT = (float2*)smem;                    // [32 p][64 l]
    #pragma unroll 1
    for (int ci = 0; ci < 4; ci++) {
        if (warp_m == ci) {
            #pragma unroll
            for (int mi = 0; mi < 4; mi++)
                #pragma unroll
                for (int j = 0; j < 2; j++)
                    #pragma unroll
                    for (int n8 = 0; n8 < 2; n8++) {
                        int g = (warp_n * 2 + j) * 2 + n8;   // 8-col group 0..7
                        int pl = g * 4 + tq;                 // local p 0..31
                        float2 cf = g_coef[p0 + pl];
                        int r0 = mi * 16 + quad;             // local l 0..63
                        float* c = acc[mi][2 * j + n8];
                        bufT[pl * 64 + r0] =
                            make_float2(c[0] * cf.x - c[1] * cf.y,
                                        c[0] * cf.y + c[1] * cf.x);
                        bufT[pl * 64 + r0 + 8] =
                            make_float2(c[2] * cf.x - c[3] * cf.y,
                                        c[2] * cf.y + c[3] * cf.x);
                    }
        }
        __syncthreads();
        {
            int pl = tid >> 3, seg = tid & 7;        // 32 rows x 8 threads
            const float4* src = (const float4*)(bufT + pl * 64);
            float4* dst = (float4*)(g_bu + (size_t)(p0 + pl) * L + l0 + ci * 64);
            #pragma unroll
            for (int q = 0; q < 4; q++) dst[seg * 4 + q] = src[seg * 4 + q];
        }
        __syncthreads();
    }
}

// ---------------------------------------------------------------------------
// Scan: x[l] = lam*x[l-1] + Bu[l], per channel, in place. 1 block/channel.
// ---------------------------------------------------------------------------
__global__ void scan_kernel() {
    __shared__ float2 sAgg[32], sBag[32];
    int p = blockIdx.x;
    float2 lam = g_lam[p];
    float2* bu = g_bu + (size_t)p * L;
    int t = threadIdx.x, lane = t & 31, warp = t >> 5;
    int base = t * 32;

    float2 b = make_float2(0.f, 0.f);
    #pragma unroll
    for (int i = 0; i < 32; i++) {
        float2 u = bu[base + i];
        b = make_float2(fmaf(lam.x, b.x, fmaf(-lam.y, b.y, u.x)),
                        fmaf(lam.x, b.y, fmaf(lam.y, b.x, u.y)));
    }
    float2 A = lam;
    #pragma unroll
    for (int i = 0; i < 5; i++) A = cmul(A, A);

    #pragma unroll
    for (int d = 1; d < 32; d <<= 1) {
        float2 Ao, bo;
        Ao.x = __shfl_up_sync(0xffffffffu, A.x, d);
        Ao.y = __shfl_up_sync(0xffffffffu, A.y, d);
        bo.x = __shfl_up_sync(0xffffffffu, b.x, d);
        bo.y = __shfl_up_sync(0xffffffffu, b.y, d);
        if (lane >= d) {
            b = make_float2(b.x + A.x * bo.x - A.y * bo.y,
                            b.y + A.x * bo.y + A.y * bo.x);
            A = cmul(A, Ao);
        }
    }
    if (lane == 31) { sAgg[warp] = A; sBag[warp] = b; }
    __syncthreads();
    if (warp == 0) {
        float2 Aw = sAgg[lane], bw = sBag[lane];
        #pragma unroll
        for (int d = 1; d < 32; d <<= 1) {
            float2 Ao, bo;
            Ao.x = __shfl_up_sync(0xffffffffu, Aw.x, d);
            Ao.y = __shfl_up_sync(0xffffffffu, Aw.y, d);
            bo.x = __shfl_up_sync(0xffffffffu, bw.x, d);
            bo.y = __shfl_up_sync(0xffffffffu, bw.y, d);
            if (lane >= d) {
                bw = make_float2(bw.x + Aw.x * bo.x - Aw.y * bo.y,
                                 bw.y + Aw.x * bo.y + Aw.y * bo.x);
                Aw = cmul(Aw, Ao);
            }
        }
        sAgg[lane] = Aw; sBag[lane] = bw;
    }
    __syncthreads();

    float2 eA, eb;
    eA.x = __shfl_up_sync(0xffffffffu, A.x, 1);
    eA.y = __shfl_up_sync(0xffffffffu, A.y, 1);
    eb.x = __shfl_up_sync(0xffffffffu, b.x, 1);
    eb.y = __shfl_up_sync(0xffffffffu, b.y, 1);
    if (lane == 0) { eA = make_float2(1.f, 0.f); eb = make_float2(0.f, 0.f); }
    float2 wb = (warp == 0) ? make_float2(0.f, 0.f) : sBag[warp - 1];
    float2 x = make_float2(eb.x + eA.x * wb.x - eA.y * wb.y,
                           eb.y + eA.x * wb.y + eA.y * wb.x);

    #pragma unroll
    for (int i = 0; i < 32; i++) {
        float2 u = bu[base + i];
        x = make_float2(fmaf(lam.x, x.x, fmaf(-lam.y, x.y, u.x)),
                        fmaf(lam.x, x.y, fmaf(lam.y, x.x, u.y)));
        bu[base + i] = x;
    }
}

// ---------------------------------------------------------------------------
// GEMM2: y = xs (Lx512 re/im-interleaved K) @ C' (512x256) + D*sig
// 256x64 CTA tile, 2-stage ring, 2 CTAs/SM.
// ---------------------------------------------------------------------------
#define G2_AB (16 * AS2B)    // 8448 floats per A stage (16 p-rows x 256 l x 2)
#define G2_BB 2048
#define G2_STG (G2_AB + G2_BB)
__global__ __launch_bounds__(256, 2) void gemm2_kernel(const float* __restrict__ sig,
                                                       const float* __restrict__ Dv,
                                                       float* __restrict__ y) {
    extern __shared__ float smem[];
    uint32_t base_u = (uint32_t)__cvta_generic_to_shared(smem);

    int tid = threadIdx.x, lane = tid & 31, wid = tid >> 5;
    int warp_m = wid & 3, warp_n = wid >> 2;
    int quad = lane >> 2, tq = lane & 3;
    int nt = blockIdx.x;                             // 64-col h tile (0..3)
    int l0 = blockIdx.y * 256;
    int h0 = nt * 64;

    float acc[4][4][4];
    #pragma unroll
    for (int mi = 0; mi < 4; mi++)
        #pragma unroll
        for (int nj = 0; nj < 4; nj++)
            #pragma unroll
            for (int q = 0; q < 4; q++) acc[mi][nj][q] = 0.f;

    auto load_chunk = [&](int kc, int sel) {
        uint32_t sA = base_u + sel * (G2_STG * 4);
        uint32_t sB = sA + G2_AB * 4;
        int p0k = kc * 16;
        #pragma unroll
        for (int i = tid; i < 2048; i += 256) {      // A: 16 p-rows x 128 segs (32 KB)
            int row = i >> 7, seg = i & 127;
            cp16(sA + (row * AS2B + seg * 4) * 4,
                 (const float*)(g_bu + (size_t)(p0k + row) * L + l0) + seg * 4);
        }
        const float* src = g_CpF + ((size_t)(nt * 16 + kc)) * 2048;
        #pragma unroll
        for (int i = tid; i < 512; i += 256)
            cp16(sB + i * 16, src + i * 4);
    };

    load_chunk(0, 0); cp_commit();
    load_chunk(1, 1); cp_commit();

    for (int kc = 0; kc < 16; kc++) {
        cp_wait<1>();
        __syncthreads();
        const float* sA = smem + (kc & 1) * G2_STG;
        const float* sB = sA + G2_AB;
        #pragma unroll
        for (int k8 = 0; k8 < 4; k8++) {
            int kb = k8 * 8;
            int kk = kb + tq;
            const float* A2 = sA + (kk >> 1) * AS2B + (kk & 1);
            unsigned a[4][4];
            #pragma unroll
            for (int mi = 0; mi < 4; mi++) {
                int r = warp_m * 64 + mi * 16 + quad;
                a[mi][0] = __float_as_uint(A2[r * 2]);
                a[mi][1] = __float_as_uint(A2[(r + 8) * 2]);
                a[mi][2] = __float_as_uint(A2[r * 2 + 2 * AS2B]);
                a[mi][3] = __float_as_uint(A2[(r + 8) * 2 + 2 * AS2B]);
            }
            #pragma unroll
            for (int j = 0; j < 2; j++) {
                float4 bq = *(const float4*)(sB + (((warp_n * 2 + j) * 4 + k8) << 7) + lane * 4);
                #pragma unroll
                for (int mi = 0; mi < 4; mi++) {
                    mma_tf32(acc[mi][2 * j],     a[mi], __float_as_uint(bq.x), __float_as_uint(bq.y));
                    mma_tf32(acc[mi][2 * j + 1], a[mi], __float_as_uint(bq.z), __float_as_uint(bq.w));
                }
            }
        }
        __syncthreads();
        if (kc + 2 < 16) load_chunk(kc + 2, kc & 1);
        cp_commit();
    }

    // Epilogue: + D*sig, direct float2 stores
    #pragma unroll
    for (int mi = 0; mi < 4; mi++)
        #pragma unroll
        for (int j = 0; j < 2; j++)
            #pragma unroll
            for (int n8 = 0; n8 < 2; n8++) {
                int l = l0 + warp_m * 64 + mi * 16 + quad;
                int h = h0 + (warp_n * 2 + j) * 16 + n8 * 8 + tq * 2;
                float d0 = Dv[h], d1 = Dv[h + 1];
                float* c = acc[mi][2 * j + n8];
                float2 s0 = *(const float2*)&sig[(size_t)l * H + h];
                *(float2*)&y[(size_t)l * H + h] =
                    make_float2(c[0] + d0 * s0.x, c[1] + d1 * s0.y);
                float2 s1 = *(const float2*)&sig[(size_t)(l + 8) * H + h];
                *(float2*)&y[(size_t)(l + 8) * H + h] =
                    make_float2(c[2] + d0 * s1.x, c[3] + d1 * s1.y);
            }
}

// ---------------------------------------------------------------------------
extern "C" void kernel_launch(void* const* d_in, const int* in_sizes, int n_in,
                              void* d_out, int out_size) {
    const float* sig = (const float*)d_in[0];
    const float* Lam = (const float*)d_in[1];
    const float* Bt  = (const float*)d_in[2];
    const float* Ct  = (const float*)d_in[3];
    const float* Dv  = (const float*)d_in[4];
    const float* ls  = (const float*)d_in[5];
    float* y = (float*)d_out;

    cudaFuncSetAttribute(gemm1_kernel, cudaFuncAttributeMaxDynamicSharedMemorySize, 2 * G1_STG * 4);
    cudaFuncSetAttribute(gemm2_kernel, cudaFuncAttributeMaxDynamicSharedMemorySize, 2 * G2_STG * 4);

    precompute_kernel<<<1, P>>>(Lam, ls);
    pack_B_kernel<<<(P * H) / 256, 256>>>(Bt);
    pack_C_kernel<<<(H * P) / 256, 256>>>(Ct);
    gemm1_kernel<<<dim3(8, L / 256), 256, 2 * G1_STG * 4>>>(sig);
    scan_kernel<<<P, 1024>>>();
    gemm2_kernel<<<dim3(4, L / 256), 256, 2 * G2_STG * 4>>>(sig, Dv, y);
}

// round 16
// speedup vs baseline: 1.4157x; 1.4157x over previous
#include <cuda_runtime.h>
#include <cstdint>

#define L 32768
#define H 256
#define P 256

// Scratch (device globals; allocation is forbidden)
__device__ __align__(16) float2   g_bu[(size_t)P * L];     // Bu then xs (fp32), (P, L)
__device__ __align__(16) uint32_t g_sigh[(size_t)L * 128]; // sig as half2 k-pairs [l][127..0]
__device__ __align__(16) uint32_t g_xsh[(size_t)P * L];    // xs as half2 (re,im) [p][l]
__device__ __align__(16) uint32_t g_BpH[8 * 8 * 1024];     // B' fp16 frag imgs [nt][kc][g][lane][4]
__device__ __align__(16) uint32_t g_CpH[4 * 16 * 1024];    // C' fp16 frag imgs
__device__ float2 g_lam[P];
__device__ float2 g_coef[P];

__device__ __forceinline__ float2 cmul(float2 a, float2 b) {
    return make_float2(a.x * b.x - a.y * b.y, a.x * b.y + a.y * b.x);
}
__device__ __forceinline__ uint32_t f2h2(float lo, float hi) {
    uint32_t u;
    asm("cvt.rn.f16x2.f32 %0, %1, %2;" : "=r"(u) : "f"(hi), "f"(lo));
    return u;
}
__device__ __forceinline__ void mma_fp16(float* c, const uint32_t* a, uint32_t b0, uint32_t b1) {
    asm volatile(
        "mma.sync.aligned.m16n8k16.row.col.f32.f16.f16.f32 "
        "{%0,%1,%2,%3}, {%4,%5,%6,%7}, {%8,%9}, {%0,%1,%2,%3};"
        : "+f"(c[0]), "+f"(c[1]), "+f"(c[2]), "+f"(c[3])
        : "r"(a[0]), "r"(a[1]), "r"(a[2]), "r"(a[3]), "r"(b0), "r"(b1));
}
__device__ __forceinline__ void cp16(uint32_t dst, const void* src) {
    asm volatile("cp.async.cg.shared.global [%0], [%1], 16;" :: "r"(dst), "l"(src));
}
__device__ __forceinline__ void cp_commit() { asm volatile("cp.async.commit_group;"); }
template<int N> __device__ __forceinline__ void cp_wait() {
    asm volatile("cp.async.wait_group %0;" :: "n"(N));
}

// ---------------------------------------------------------------------------
// ZOH discretization
// ---------------------------------------------------------------------------
__global__ void precompute_kernel(const float* __restrict__ Lambda_ri,
                                  const float* __restrict__ log_step) {
    int p = threadIdx.x;
    float lr = Lambda_ri[2 * p], li = Lambda_ri[2 * p + 1];
    float dt = expf(log_step[p]);
    float mag = expf(lr * dt);
    float s, c;
    sincosf(li * dt, &s, &c);
    float2 lam = make_float2(mag * c, mag * s);
    float2 num = make_float2(lam.x - 1.0f, lam.y);
    float inv = 1.0f / (lr * lr + li * li);
    g_lam[p] = lam;
    g_coef[p] = make_float2((num.x * lr + num.y * li) * inv,
                            (num.y * lr - num.x * li) * inv);
}

// sig (L x 256 fp32) -> half2 pairs [l][128]
__global__ void pack_sig_kernel(const float* __restrict__ sig) {
    size_t i = (size_t)blockIdx.x * 256 + threadIdx.x;     // i < L*128
    float2 v = *(const float2*)(sig + i * 2);
    g_sigh[i] = f2h2(v.x, v.y);
}

// B' fp16 fragment images. n = 2p+c (N=512), k = h (K=256).
// Image per (nt 0..7, kc 0..7): [g 0..7][lane 0..31][b0s0,b1s0,b0s1,b1s1]
__global__ void pack_BH_kernel(const float* __restrict__ B_ri) {
    int idx = blockIdx.x * 256 + threadIdx.x;              // 16384 threads
    int lane = idx & 31, g = (idx >> 5) & 7, kc = (idx >> 8) & 7, nt = idx >> 11;
    int t = lane & 3, grp = lane >> 2;
    int n = nt * 64 + g * 8 + grp;
    int p = n >> 1, c = n & 1;
    #pragma unroll
    for (int q = 0; q < 4; q++) {
        int s = q >> 1, r01 = q & 1;
        int h = kc * 32 + s * 16 + r01 * 8 + 2 * t;
        float v0 = B_ri[((size_t)p * 256 + h) * 2 + c];
        float v1 = B_ri[((size_t)p * 256 + h + 1) * 2 + c];
        g_BpH[(size_t)idx * 4 + q] = f2h2(v0, v1);
    }
}

// C' fp16 fragment images. n = h (N=256), k = 2p+c (K=512); c=0 -> Cre, c=1 -> -Cim.
// Image per (nt 0..3, kc 0..15).
__global__ void pack_CH_kernel(const float* __restrict__ C_ri) {
    int idx = blockIdx.x * 256 + threadIdx.x;              // 16384 threads
    int lane = idx & 31, g = (idx >> 5) & 7, kc = (idx >> 8) & 15, nt = idx >> 12;
    int t = lane & 3, grp = lane >> 2;
    int h = nt * 64 + g * 8 + grp;
    #pragma unroll
    for (int q = 0; q < 4; q++) {
        int s = q >> 1, r01 = q & 1;
        int p = kc * 16 + s * 8 + r01 * 4 + t;             // k0 = 2p (c=0), k0+1 = c=1
        float re = C_ri[((size_t)h * 256 + p) * 2 + 0];
        float im = C_ri[((size_t)h * 256 + p) * 2 + 1];
        g_CpH[(size_t)idx * 4 + q] = f2h2(re, -im);
    }
}

// ---------------------------------------------------------------------------
// GEMM1: Bu = sig (Lx256) @ B' (256x512), fp16 mma.m16n8k16.
// 128x64 CTA tile, 8 warps (4x2, 32x32 each), 2-stage ring, 3 CTAs/SM.
// A smem: 128 rows x 20 u32 (16 data + 4 pad). B smem: 1024 u32 image copy.
// ---------------------------------------------------------------------------
#define G1_AW 2560           // 128*20 u32 per A stage
#define G1_BW 1024
#define G1_STGW (G1_AW + G1_BW)
__global__ __launch_bounds__(256, 3) void gemm1_kernel() {
    extern __shared__ uint32_t smw[];
    uint32_t base_u = (uint32_t)__cvta_generic_to_shared(smw);

    int tid = threadIdx.x, lane = tid & 31, wid = tid >> 5;
    int warp_m = wid & 3, warp_n = wid >> 2;        // 4 x 2
    int quad = lane >> 2, tq = lane & 3;
    int nt = blockIdx.x;                             // 64-col n tile (0..7)
    int l0 = blockIdx.y * 128;

    float acc[2][4][4];
    #pragma unroll
    for (int mi = 0; mi < 2; mi++)
        #pragma unroll
        for (int nj = 0; nj < 4; nj++)
            #pragma unroll
            for (int q = 0; q < 4; q++) acc[mi][nj][q] = 0.f;

    auto load_chunk = [&](int kc, int sel) {
        uint32_t sA = base_u + sel * (G1_STGW * 4);
        uint32_t sB = sA + G1_AW * 4;
        #pragma unroll
        for (int i = tid; i < 512; i += 256) {       // A: 128 rows x 4 segs (8 KB)
            int row = i >> 2, seg = i & 3;
            cp16(sA + (row * 20 + seg * 4) * 4,
                 g_sigh + (size_t)(l0 + row) * 128 + kc * 16 + seg * 4);
        }
        const uint32_t* src = g_BpH + ((size_t)(nt * 8 + kc)) * 1024;
        cp16(sB + tid * 16, src + tid * 4);          // B: 1024 u32 = 256 x 16B
    };

    load_chunk(0, 0); cp_commit();
    load_chunk(1, 1); cp_commit();

    for (int kc = 0; kc < 8; kc++) {
        cp_wait<1>();
        __syncthreads();
        const uint32_t* sA = smw + (kc & 1) * G1_STGW;
        const uint32_t* sB = sA + G1_AW;
        float4 bq[4];
        #pragma unroll
        for (int j = 0; j < 4; j++)
            bq[j] = *(const float4*)(sB + (warp_n * 4 + j) * 128 + lane * 4);
        #pragma unroll
        for (int s = 0; s < 2; s++) {
            uint32_t a[2][4];
            #pragma unroll
            for (int mi = 0; mi < 2; mi++) {
                int r = warp_m * 32 + mi * 16 + quad;
                a[mi][0] = sA[r * 20 + s * 8 + tq];
                a[mi][1] = sA[(r + 8) * 20 + s * 8 + tq];
                a[mi][2] = sA[r * 20 + s * 8 + tq + 4];
                a[mi][3] = sA[(r + 8) * 20 + s * 8 + tq + 4];
            }
            #pragma unroll
            for (int j = 0; j < 4; j++) {
                uint32_t b0 = s ? __float_as_uint(bq[j].z) : __float_as_uint(bq[j].x);
                uint32_t b1 = s ? __float_as_uint(bq[j].w) : __float_as_uint(bq[j].y);
                #pragma unroll
                for (int mi = 0; mi < 2; mi++)
                    mma_fp16(acc[mi][j], a[mi], b0, b1);
            }
        }
        __syncthreads();
        if (kc + 2 < 8) load_chunk(kc + 2, kc & 1);
        cp_commit();
    }

    // Epilogue: complex coef, transpose through smem, coalesced (P,L) stores
    int p0 = nt * 32;
    float2* bufT = (float2*)smw;                     // [32 p][32 l]
    #pragma unroll 1
    for (int ci = 0; ci < 4; ci++) {
        if (warp_m == ci) {
            #pragma unroll
            for (int mi = 0; mi < 2; mi++)
                #pragma unroll
                for (int j = 0; j < 4; j++) {
                    int pl = (warp_n * 4 + j) * 4 + tq;  // local p 0..31
                    float2 cf = g_coef[p0 + pl];
                    int r0 = mi * 16 + quad;
                    float* c = acc[mi][j];
                    bufT[pl * 32 + r0] =
                        make_float2(c[0] * cf.x - c[1] * cf.y,
                                    c[0] * cf.y + c[1] * cf.x);
                    bufT[pl * 32 + r0 + 8] =
                        make_float2(c[2] * cf.x - c[3] * cf.y,
                                    c[2] * cf.y + c[3] * cf.x);
                }
        }
        __syncthreads();
        {
            int pl = tid >> 3, seg = tid & 7;        // 32 rows x 8 threads
            const float4* src = (const float4*)(bufT + pl * 32);
            float4* dst = (float4*)(g_bu + (size_t)(p0 + pl) * L + l0 + ci * 32);
            #pragma unroll
            for (int q = 0; q < 2; q++) dst[seg * 2 + q] = src[seg * 2 + q];
        }
        __syncthreads();
    }
}

// ---------------------------------------------------------------------------
// Scan: x[l] = lam*x[l-1] + Bu[l], per channel, in place; also emit half2 xs.
// ---------------------------------------------------------------------------
__global__ void scan_kernel() {
    __shared__ float2 sAgg[32], sBag[32];
    int p = blockIdx.x;
    float2 lam = g_lam[p];
    float2* bu = g_bu + (size_t)p * L;
    uint32_t* xh = g_xsh + (size_t)p * L;
    int t = threadIdx.x, lane = t & 31, warp = t >> 5;
    int base = t * 32;

    float2 b = make_float2(0.f, 0.f);
    #pragma unroll
    for (int i = 0; i < 32; i++) {
        float2 u = bu[base + i];
        b = make_float2(fmaf(lam.x, b.x, fmaf(-lam.y, b.y, u.x)),
                        fmaf(lam.x, b.y, fmaf(lam.y, b.x, u.y)));
    }
    float2 A = lam;
    #pragma unroll
    for (int i = 0; i < 5; i++) A = cmul(A, A);

    #pragma unroll
    for (int d = 1; d < 32; d <<= 1) {
        float2 Ao, bo;
        Ao.x = __shfl_up_sync(0xffffffffu, A.x, d);
        Ao.y = __shfl_up_sync(0xffffffffu, A.y, d);
        bo.x = __shfl_up_sync(0xffffffffu, b.x, d);
        bo.y = __shfl_up_sync(0xffffffffu, b.y, d);
        if (lane >= d) {
            b = make_float2(b.x + A.x * bo.x - A.y * bo.y,
                            b.y + A.x * bo.y + A.y * bo.x);
            A = cmul(A, Ao);
        }
    }
    if (lane == 31) { sAgg[warp] = A; sBag[warp] = b; }
    __syncthreads();
    if (warp == 0) {
        float2 Aw = sAgg[lane], bw = sBag[lane];
        #pragma unroll
        for (int d = 1; d < 32; d <<= 1) {
            float2 Ao, bo;
            Ao.x = __shfl_up_sync(0xffffffffu, Aw.x, d);
            Ao.y = __shfl_up_sync(0xffffffffu, Aw.y, d);
            bo.x = __shfl_up_sync(0xffffffffu, bw.x, d);
            bo.y = __shfl_up_sync(0xffffffffu, bw.y, d);
            if (lane >= d) {
                bw = make_float2(bw.x + Aw.x * bo.x - Aw.y * bo.y,
                                 bw.y + Aw.x * bo.y + Aw.y * bo.x);
                Aw = cmul(Aw, Ao);
            }
        }
        sAgg[lane] = Aw; sBag[lane] = bw;
    }
    __syncthreads();

    float2 eA, eb;
    eA.x = __shfl_up_sync(0xffffffffu, A.x, 1);
    eA.y = __shfl_up_sync(0xffffffffu, A.y, 1);
    eb.x = __shfl_up_sync(0xffffffffu, b.x, 1);
    eb.y = __shfl_up_sync(0xffffffffu, b.y, 1);
    if (lane == 0) { eA = make_float2(1.f, 0.f); eb = make_float2(0.f, 0.f); }
    float2 wb = (warp == 0) ? make_float2(0.f, 0.f) : sBag[warp - 1];
    float2 x = make_float2(eb.x + eA.x * wb.x - eA.y * wb.y,
                           eb.y + eA.x * wb.y + eA.y * wb.x);

    #pragma unroll
    for (int i = 0; i < 32; i++) {
        float2 u = bu[base + i];
        x = make_float2(fmaf(lam.x, x.x, fmaf(-lam.y, x.y, u.x)),
                        fmaf(lam.x, x.y, fmaf(lam.y, x.x, u.y)));
        xh[base + i] = f2h2(x.x, x.y);
    }
}

// ---------------------------------------------------------------------------
// GEMM2: y = xs (Lx512 interleaved K) @ C' (512x256) + D*sig, fp16 mma.
// A smem: 16 p-rows x 136 u32 (128 data + 8 pad). 2-stage ring, 3 CTAs/SM.
// ---------------------------------------------------------------------------
#define G2_AW 2176           // 16*136 u32 per A stage
#define G2_BW 1024
#define G2_STGW (G2_AW + G2_BW)
__global__ __launch_bounds__(256, 3) void gemm2_kernel(const float* __restrict__ sig,
                                                       const float* __restrict__ Dv,
                                                       float* __restrict__ y) {
    extern __shared__ uint32_t smw[];
    uint32_t base_u = (uint32_t)__cvta_generic_to_shared(smw);

    int tid = threadIdx.x, lane = tid & 31, wid = tid >> 5;
    int warp_m = wid & 3, warp_n = wid >> 2;
    int quad = lane >> 2, tq = lane & 3;
    int nt = blockIdx.x;                             // 64-col h tile (0..3)
    int l0 = blockIdx.y * 128;
    int h0 = nt * 64;

    float acc[2][4][4];
    #pragma unroll
    for (int mi = 0; mi < 2; mi++)
        #pragma unroll
        for (int nj = 0; nj < 4; nj++)
            #pragma unroll
            for (int q = 0; q < 4; q++) acc[mi][nj][q] = 0.f;

    auto load_chunk = [&](int kc, int sel) {
        uint32_t sA = base_u + sel * (G2_STGW * 4);
        uint32_t sB = sA + G2_AW * 4;
        int p0k = kc * 16;
        #pragma unroll
        for (int i = tid; i < 512; i += 256) {       // A: 16 rows x 32 segs (8 KB)
            int row = i >> 5, seg = i & 31;
            cp16(sA + (row * 136 + seg * 4) * 4,
                 g_xsh + (size_t)(p0k + row) * L + l0 + seg * 4);
        }
        const uint32_t* src = g_CpH + ((size_t)(nt * 16 + kc)) * 1024;
        cp16(sB + tid * 16, src + tid * 4);
    };

    load_chunk(0, 0); cp_commit();
    load_chunk(1, 1); cp_commit();

    for (int kc = 0; kc < 16; kc++) {
        cp_wait<1>();
        __syncthreads();
        const uint32_t* sA = smw + (kc & 1) * G2_STGW;
        const uint32_t* sB = sA + G2_AW;
        float4 bq[4];
        #pragma unroll
        for (int j = 0; j < 4; j++)
            bq[j] = *(const float4*)(sB + (warp_n * 4 + j) * 128 + lane * 4);
        #pragma unroll
        for (int s = 0; s < 2; s++) {
            uint32_t a[2][4];
            #pragma unroll
            for (int mi = 0; mi < 2; mi++) {
                int lrow = warp_m * 32 + mi * 16 + quad;
                a[mi][0] = sA[(s * 8 + tq) * 136 + lrow];
                a[mi][1] = sA[(s * 8 + tq) * 136 + lrow + 8];
                a[mi][2] = sA[(s * 8 + tq + 4) * 136 + lrow];
                a[mi][3] = sA[(s * 8 + tq + 4) * 136 + lrow + 8];
            }
            #pragma unroll
            for (int j = 0; j < 4; j++) {
                uint32_t b0 = s ? __float_as_uint(bq[j].z) : __float_as_uint(bq[j].x);
                uint32_t b1 = s ? __float_as_uint(bq[j].w) : __float_as_uint(bq[j].y);
                #pragma unroll
                for (int mi = 0; mi < 2; mi++)
                    mma_fp16(acc[mi][j], a[mi], b0, b1);
            }
        }
        __syncthreads();
        if (kc + 2 < 16) load_chunk(kc + 2, kc & 1);
        cp_commit();
    }

    // Epilogue: + D*sig, direct float2 stores
    #pragma unroll
    for (int mi = 0; mi < 2; mi++)
        #pragma unroll
        for (int j = 0; j < 4; j++) {
            int l = l0 + warp_m * 32 + mi * 16 + quad;
            int h = h0 + (warp_n * 4 + j) * 8 + tq * 2;
            float d0 = Dv[h], d1 = Dv[h + 1];
            float* c = acc[mi][j];
            float2 s0 = *(const float2*)&sig[(size_t)l * H + h];
            *(float2*)&y[(size_t)l * H + h] =
                make_float2(c[0] + d0 * s0.x, c[1] + d1 * s0.y);
            float2 s1 = *(const float2*)&sig[(size_t)(l + 8) * H + h];
            *(float2*)&y[(size_t)(l + 8) * H + h] =
                make_float2(c[2] + d0 * s1.x, c[3] + d1 * s1.y);
        }
}

// ---------------------------------------------------------------------------
extern "C" void kernel_launch(void* const* d_in, const int* in_sizes, int n_in,
                              void* d_out, int out_size) {
    const float* sig = (const float*)d_in[0];
    const float* Lam = (const float*)d_in[1];
    const float* Bt  = (const float*)d_in[2];
    const float* Ct  = (const float*)d_in[3];
    const float* Dv  = (const float*)d_in[4];
    const float* ls  = (const float*)d_in[5];
    float* y = (float*)d_out;

    cudaFuncSetAttribute(gemm1_kernel, cudaFuncAttributeMaxDynamicSharedMemorySize, 2 * G1_STGW * 4);
    cudaFuncSetAttribute(gemm2_kernel, cudaFuncAttributeMaxDynamicSharedMemorySize, 2 * G2_STGW * 4);

    precompute_kernel<<<1, P>>>(Lam, ls);
    pack_sig_kernel<<<(L * 128) / 256, 256>>>(sig);
    pack_BH_kernel<<<64, 256>>>(Bt);
    pack_CH_kernel<<<64, 256>>>(Ct);
    gemm1_kernel<<<dim3(8, L / 128), 256, 2 * G1_STGW * 4>>>();
    scan_kernel<<<P, 1024>>>();
    gemm2_kernel<<<dim3(4, L / 128), 256, 2 * G2_STGW * 4>>>(sig, Dv, y);
}

// round 17
// speedup vs baseline: 1.6988x; 1.2000x over previous
#include <cuda_runtime.h>
#include <cuda_fp16.h>
#include <cstdint>

#define L 32768
#define H 256
#define P 256

// Scratch (device globals; allocation is forbidden)
__device__ __align__(16) uint32_t g_sigh[(size_t)L * 128]; // sig as half2 k-pairs [l][127..0]
__device__ __align__(16) uint32_t g_xsh[(size_t)P * L];    // Bu then xs, half2 (re,im) [p][l]
__device__ __align__(16) uint32_t g_BpH[8 * 8 * 1024];     // B' fp16 frag imgs [nt][kc][g][lane][4]
__device__ __align__(16) uint32_t g_CpH[4 * 16 * 1024];    // C' fp16 frag imgs
__device__ float2 g_lam[P];
__device__ float2 g_coef[P];

__device__ __forceinline__ float2 cmul(float2 a, float2 b) {
    return make_float2(a.x * b.x - a.y * b.y, a.x * b.y + a.y * b.x);
}
__device__ __forceinline__ uint32_t f2h2(float lo, float hi) {
    uint32_t u;
    asm("cvt.rn.f16x2.f32 %0, %1, %2;" : "=r"(u) : "f"(hi), "f"(lo));
    return u;
}
__device__ __forceinline__ float2 h2f2(uint32_t u) {
    __half2 h = *reinterpret_cast<__half2*>(&u);
    return __half22float2(h);
}
__device__ __forceinline__ void mma_fp16(float* c, const uint32_t* a, uint32_t b0, uint32_t b1) {
    asm volatile(
        "mma.sync.aligned.m16n8k16.row.col.f32.f16.f16.f32 "
        "{%0,%1,%2,%3}, {%4,%5,%6,%7}, {%8,%9}, {%0,%1,%2,%3};"
        : "+f"(c[0]), "+f"(c[1]), "+f"(c[2]), "+f"(c[3])
        : "r"(a[0]), "r"(a[1]), "r"(a[2]), "r"(a[3]), "r"(b0), "r"(b1));
}
__device__ __forceinline__ void cp16(uint32_t dst, const void* src) {
    asm volatile("cp.async.cg.shared.global [%0], [%1], 16;" :: "r"(dst), "l"(src));
}
__device__ __forceinline__ void cp_commit() { asm volatile("cp.async.commit_group;"); }
template<int N> __device__ __forceinline__ void cp_wait() {
    asm volatile("cp.async.wait_group %0;" :: "n"(N));
}

// ---------------------------------------------------------------------------
// ZOH discretization
// ---------------------------------------------------------------------------
__global__ void precompute_kernel(const float* __restrict__ Lambda_ri,
                                  const float* __restrict__ log_step) {
    int p = threadIdx.x;
    float lr = Lambda_ri[2 * p], li = Lambda_ri[2 * p + 1];
    float dt = expf(log_step[p]);
    float mag = expf(lr * dt);
    float s, c;
    sincosf(li * dt, &s, &c);
    float2 lam = make_float2(mag * c, mag * s);
    float2 num = make_float2(lam.x - 1.0f, lam.y);
    float inv = 1.0f / (lr * lr + li * li);
    g_lam[p] = lam;
    g_coef[p] = make_float2((num.x * lr + num.y * li) * inv,
                            (num.y * lr - num.x * li) * inv);
}

// sig (L x 256 fp32) -> half2 pairs [l][128]
__global__ void pack_sig_kernel(const float* __restrict__ sig) {
    size_t i = (size_t)blockIdx.x * 256 + threadIdx.x;     // i < L*128
    float2 v = *(const float2*)(sig + i * 2);
    g_sigh[i] = f2h2(v.x, v.y);
}

// B' fp16 fragment images. n = 2p+c (N=512), k = h (K=256).
// Image per (nt 0..7, kc 0..7): [g 0..7][lane 0..31][b0s0,b1s0,b0s1,b1s1]
__global__ void pack_BH_kernel(const float* __restrict__ B_ri) {
    int idx = blockIdx.x * 256 + threadIdx.x;              // 16384 threads
    int lane = idx & 31, g = (idx >> 5) & 7, kc = (idx >> 8) & 7, nt = idx >> 11;
    int t = lane & 3, grp = lane >> 2;
    int n = nt * 64 + g * 8 + grp;
    int p = n >> 1, c = n & 1;
    #pragma unroll
    for (int q = 0; q < 4; q++) {
        int s = q >> 1, r01 = q & 1;
        int h = kc * 32 + s * 16 + r01 * 8 + 2 * t;
        float v0 = B_ri[((size_t)p * 256 + h) * 2 + c];
        float v1 = B_ri[((size_t)p * 256 + h + 1) * 2 + c];
        g_BpH[(size_t)idx * 4 + q] = f2h2(v0, v1);
    }
}

// C' fp16 fragment images. n = h (N=256), k = 2p+c (K=512); c=0 -> Cre, c=1 -> -Cim.
__global__ void pack_CH_kernel(const float* __restrict__ C_ri) {
    int idx = blockIdx.x * 256 + threadIdx.x;              // 16384 threads
    int lane = idx & 31, g = (idx >> 5) & 7, kc = (idx >> 8) & 15, nt = idx >> 12;
    int t = lane & 3, grp = lane >> 2;
    int h = nt * 64 + g * 8 + grp;
    #pragma unroll
    for (int q = 0; q < 4; q++) {
        int s = q >> 1, r01 = q & 1;
        int p = kc * 16 + s * 8 + r01 * 4 + t;
        float re = C_ri[((size_t)h * 256 + p) * 2 + 0];
        float im = C_ri[((size_t)h * 256 + p) * 2 + 1];
        g_CpH[(size_t)idx * 4 + q] = f2h2(re, -im);
    }
}

// ---------------------------------------------------------------------------
// GEMM1: Bu = sig (Lx256) @ B' (256x512), fp16 mma.m16n8k16.
// 128x64 CTA tile, 8 warps (4x2, 32x32 each), 2-stage ring, 3 CTAs/SM.
// Epilogue writes half2 Bu directly into g_xsh (channel-major).
// ---------------------------------------------------------------------------
#define G1_AW 2560           // 128*20 u32 per A stage
#define G1_BW 1024
#define G1_STGW (G1_AW + G1_BW)
__global__ __launch_bounds__(256, 3) void gemm1_kernel() {
    extern __shared__ uint32_t smw[];
    uint32_t base_u = (uint32_t)__cvta_generic_to_shared(smw);

    int tid = threadIdx.x, lane = tid & 31, wid = tid >> 5;
    int warp_m = wid & 3, warp_n = wid >> 2;        // 4 x 2
    int quad = lane >> 2, tq = lane & 3;
    int nt = blockIdx.x;                             // 64-col n tile (0..7)
    int l0 = blockIdx.y * 128;

    float acc[2][4][4];
    #pragma unroll
    for (int mi = 0; mi < 2; mi++)
        #pragma unroll
        for (int nj = 0; nj < 4; nj++)
            #pragma unroll
            for (int q = 0; q < 4; q++) acc[mi][nj][q] = 0.f;

    auto load_chunk = [&](int kc, int sel) {
        uint32_t sA = base_u + sel * (G1_STGW * 4);
        uint32_t sB = sA + G1_AW * 4;
        #pragma unroll
        for (int i = tid; i < 512; i += 256) {       // A: 128 rows x 4 segs (8 KB)
            int row = i >> 2, seg = i & 3;
            cp16(sA + (row * 20 + seg * 4) * 4,
                 g_sigh + (size_t)(l0 + row) * 128 + kc * 16 + seg * 4);
        }
        const uint32_t* src = g_BpH + ((size_t)(nt * 8 + kc)) * 1024;
        cp16(sB + tid * 16, src + tid * 4);          // B: 1024 u32 = 256 x 16B
    };

    load_chunk(0, 0); cp_commit();
    load_chunk(1, 1); cp_commit();

    for (int kc = 0; kc < 8; kc++) {
        cp_wait<1>();
        __syncthreads();
        const uint32_t* sA = smw + (kc & 1) * G1_STGW;
        const uint32_t* sB = sA + G1_AW;
        float4 bq[4];
        #pragma unroll
        for (int j = 0; j < 4; j++)
            bq[j] = *(const float4*)(sB + (warp_n * 4 + j) * 128 + lane * 4);
        #pragma unroll
        for (int s = 0; s < 2; s++) {
            uint32_t a[2][4];
            #pragma unroll
            for (int mi = 0; mi < 2; mi++) {
                int r = warp_m * 32 + mi * 16 + quad;
                a[mi][0] = sA[r * 20 + s * 8 + tq];
                a[mi][1] = sA[(r + 8) * 20 + s * 8 + tq];
                a[mi][2] = sA[r * 20 + s * 8 + tq + 4];
                a[mi][3] = sA[(r + 8) * 20 + s * 8 + tq + 4];
            }
            #pragma unroll
            for (int j = 0; j < 4; j++) {
                uint32_t b0 = s ? __float_as_uint(bq[j].z) : __float_as_uint(bq[j].x);
                uint32_t b1 = s ? __float_as_uint(bq[j].w) : __float_as_uint(bq[j].y);
                #pragma unroll
                for (int mi = 0; mi < 2; mi++)
                    mma_fp16(acc[mi][j], a[mi], b0, b1);
            }
        }
        __syncthreads();
        if (kc + 2 < 8) load_chunk(kc + 2, kc & 1);
        cp_commit();
    }

    // Epilogue: complex coef -> half2, transpose via smem, coalesced (P,L) stores
    int p0 = nt * 32;
    uint32_t* bufT = smw;                            // [32 p][stride 36]
    #pragma unroll 1
    for (int ci = 0; ci < 4; ci++) {
        if (warp_m == ci) {
            #pragma unroll
            for (int mi = 0; mi < 2; mi++)
                #pragma unroll
                for (int j = 0; j < 4; j++) {
                    int pl = (warp_n * 4 + j) * 4 + tq;  // local p 0..31
                    float2 cf = g_coef[p0 + pl];
                    int r0 = mi * 16 + quad;
                    float* c = acc[mi][j];
                    bufT[pl * 36 + r0] =
                        f2h2(c[0] * cf.x - c[1] * cf.y, c[0] * cf.y + c[1] * cf.x);
                    bufT[pl * 36 + r0 + 8] =
                        f2h2(c[2] * cf.x - c[3] * cf.y, c[2] * cf.y + c[3] * cf.x);
                }
        }
        __syncthreads();
        {
            int pl = tid >> 3, seg = tid & 7;        // 32 rows x 8 threads
            const uint4* src = (const uint4*)(bufT + pl * 36);
            uint4* dst = (uint4*)(g_xsh + (size_t)(p0 + pl) * L + l0 + ci * 32);
            dst[seg] = src[seg];
        }
        __syncthreads();
    }
}

// ---------------------------------------------------------------------------
// Scan: x[l] = lam*x[l-1] + Bu[l] per channel, fp32 accum, half2 in/out,
// IN PLACE on g_xsh. 256 blocks x 512 threads x 64 items.
// ---------------------------------------------------------------------------
__global__ __launch_bounds__(512) void scan_kernel() {
    __shared__ float2 sAgg[16], sBag[16];
    int p = blockIdx.x;
    float2 lam = g_lam[p];
    uint32_t* xh = g_xsh + (size_t)p * L;
    int t = threadIdx.x, lane = t & 31, warp = t >> 5;
    int base = t * 64;

    // Pass 1: thread-local aggregate
    float2 b = make_float2(0.f, 0.f);
    #pragma unroll 8
    for (int i = 0; i < 64; i++) {
        float2 u = h2f2(xh[base + i]);
        b = make_float2(fmaf(lam.x, b.x, fmaf(-lam.y, b.y, u.x)),
                        fmaf(lam.x, b.y, fmaf(lam.y, b.x, u.y)));
    }
    // A = lam^64
    float2 A = lam;
    #pragma unroll
    for (int i = 0; i < 6; i++) A = cmul(A, A);

    // Warp inclusive scan of (A, b)
    #pragma unroll
    for (int d = 1; d < 32; d <<= 1) {
        float2 Ao, bo;
        Ao.x = __shfl_up_sync(0xffffffffu, A.x, d);
        Ao.y = __shfl_up_sync(0xffffffffu, A.y, d);
        bo.x = __shfl_up_sync(0xffffffffu, b.x, d);
        bo.y = __shfl_up_sync(0xffffffffu, b.y, d);
        if (lane >= d) {
            b = make_float2(b.x + A.x * bo.x - A.y * bo.y,
                            b.y + A.x * bo.y + A.y * bo.x);
            A = cmul(A, Ao);
        }
    }
    if (lane == 31) { sAgg[warp] = A; sBag[warp] = b; }
    __syncthreads();
    // Cross-warp scan (16 aggregates, warp 0)
    if (warp == 0 && lane < 16) {
        float2 Aw = sAgg[lane], bw = sBag[lane];
        #pragma unroll
        for (int d = 1; d < 16; d <<= 1) {
            float2 Ao, bo;
            Ao.x = __shfl_up_sync(0x0000ffffu, Aw.x, d);
            Ao.y = __shfl_up_sync(0x0000ffffu, Aw.y, d);
            bo.x = __shfl_up_sync(0x0000ffffu, bw.x, d);
            bo.y = __shfl_up_sync(0x0000ffffu, bw.y, d);
            if (lane >= d) {
                bw = make_float2(bw.x + Aw.x * bo.x - Aw.y * bo.y,
                                 bw.y + Aw.x * bo.y + Aw.y * bo.x);
                Aw = cmul(Aw, Ao);
            }
        }
        sAgg[lane] = Aw; sBag[lane] = bw;
    }
    __syncthreads();

    // Exclusive prefix entering this thread's segment
    float2 eA, eb;
    eA.x = __shfl_up_sync(0xffffffffu, A.x, 1);
    eA.y = __shfl_up_sync(0xffffffffu, A.y, 1);
    eb.x = __shfl_up_sync(0xffffffffu, b.x, 1);
    eb.y = __shfl_up_sync(0xffffffffu, b.y, 1);
    if (lane == 0) { eA = make_float2(1.f, 0.f); eb = make_float2(0.f, 0.f); }
    float2 wb = (warp == 0) ? make_float2(0.f, 0.f) : sBag[warp - 1];
    float2 x = make_float2(eb.x + eA.x * wb.x - eA.y * wb.y,
                           eb.y + eA.x * wb.y + eA.y * wb.x);

    // Pass 2: fix-up, overwrite in place with xs (half2)
    #pragma unroll 8
    for (int i = 0; i < 64; i++) {
        float2 u = h2f2(xh[base + i]);
        x = make_float2(fmaf(lam.x, x.x, fmaf(-lam.y, x.y, u.x)),
                        fmaf(lam.x, x.y, fmaf(lam.y, x.x, u.y)));
        xh[base + i] = f2h2(x.x, x.y);
    }
}

// ---------------------------------------------------------------------------
// GEMM2: y = xs (Lx512 interleaved K) @ C' (512x256) + D*sig, fp16 mma.
// A smem: 16 p-rows x 136 u32 (128 data + 8 pad). 2-stage ring, 3 CTAs/SM.
// ---------------------------------------------------------------------------
#define G2_AW 2176           // 16*136 u32 per A stage
#define G2_BW 1024
#define G2_STGW (G2_AW + G2_BW)
__global__ __launch_bounds__(256, 3) void gemm2_kernel(const float* __restrict__ sig,
                                                       const float* __restrict__ Dv,
                                                       float* __restrict__ y) {
    extern __shared__ uint32_t smw[];
    uint32_t base_u = (uint32_t)__cvta_generic_to_shared(smw);

    int tid = threadIdx.x, lane = tid & 31, wid = tid >> 5;
    int warp_m = wid & 3, warp_n = wid >> 2;
    int quad = lane >> 2, tq = lane & 3;
    int nt = blockIdx.x;                             // 64-col h tile (0..3)
    int l0 = blockIdx.y * 128;
    int h0 = nt * 64;

    float acc[2][4][4];
    #pragma unroll
    for (int mi = 0; mi < 2; mi++)
        #pragma unroll
        for (int nj = 0; nj < 4; nj++)
            #pragma unroll
            for (int q = 0; q < 4; q++) acc[mi][nj][q] = 0.f;

    auto load_chunk = [&](int kc, int sel) {
        uint32_t sA = base_u + sel * (G2_STGW * 4);
        uint32_t sB = sA + G2_AW * 4;
        int p0k = kc * 16;
        #pragma unroll
        for (int i = tid; i < 512; i += 256) {       // A: 16 rows x 32 segs (8 KB)
            int row = i >> 5, seg = i & 31;
            cp16(sA + (row * 136 + seg * 4) * 4,
                 g_xsh + (size_t)(p0k + row) * L + l0 + seg * 4);
        }
        const uint32_t* src = g_CpH + ((size_t)(nt * 16 + kc)) * 1024;
        cp16(sB + tid * 16, src + tid * 4);
    };

    load_chunk(0, 0); cp_commit();
    load_chunk(1, 1); cp_commit();

    for (int kc = 0; kc < 16; kc++) {
        cp_wait<1>();
        __syncthreads();
        const uint32_t* sA = smw + (kc & 1) * G2_STGW;
        const uint32_t* sB = sA + G2_AW;
        float4 bq[4];
        #pragma unroll
        for (int j = 0; j < 4; j++)
            bq[j] = *(const float4*)(sB + (warp_n * 4 + j) * 128 + lane * 4);
        #pragma unroll
        for (int s = 0; s < 2; s++) {
            uint32_t a[2][4];
            #pragma unroll
            for (int mi = 0; mi < 2; mi++) {
                int lrow = warp_m * 32 + mi * 16 + quad;
                a[mi][0] = sA[(s * 8 + tq) * 136 + lrow];
                a[mi][1] = sA[(s * 8 + tq) * 136 + lrow + 8];
                a[mi][2] = sA[(s * 8 + tq + 4) * 136 + lrow];
                a[mi][3] = sA[(s * 8 + tq + 4) * 136 + lrow + 8];
            }
            #pragma unroll
            for (int j = 0; j < 4; j++) {
                uint32_t b0 = s ? __float_as_uint(bq[j].z) : __float_as_uint(bq[j].x);
                uint32_t b1 = s ? __float_as_uint(bq[j].w) : __float_as_uint(bq[j].y);
                #pragma unroll
                for (int mi = 0; mi < 2; mi++)
                    mma_fp16(acc[mi][j], a[mi], b0, b1);
            }
        }
        __syncthreads();
        if (kc + 2 < 16) load_chunk(kc + 2, kc & 1);
        cp_commit();
    }

    // Epilogue: + D*sig, direct float2 stores
    #pragma unroll
    for (int mi = 0; mi < 2; mi++)
        #pragma unroll
        for (int j = 0; j < 4; j++) {
            int l = l0 + warp_m * 32 + mi * 16 + quad;
            int h = h0 + (warp_n * 4 + j) * 8 + tq * 2;
            float d0 = Dv[h], d1 = Dv[h + 1];
            float* c = acc[mi][j];
            float2 s0 = *(const float2*)&sig[(size_t)l * H + h];
            *(float2*)&y[(size_t)l * H + h] =
                make_float2(c[0] + d0 * s0.x, c[1] + d1 * s0.y);
            float2 s1 = *(const float2*)&sig[(size_t)(l + 8) * H + h];
            *(float2*)&y[(size_t)(l + 8) * H + h] =
                make_float2(c[2] + d0 * s1.x, c[3] + d1 * s1.y);
        }
}

// ---------------------------------------------------------------------------
extern "C" void kernel_launch(void* const* d_in, const int* in_sizes, int n_in,
                              void* d_out, int out_size) {
    const float* sig = (const float*)d_in[0];
    const float* Lam = (const float*)d_in[1];
    const float* Bt  = (const float*)d_in[2];
    const float* Ct  = (const float*)d_in[3];
    const float* Dv  = (const float*)d_in[4];
    const float* ls  = (const float*)d_in[5];
    float* y = (float*)d_out;

    cudaFuncSetAttribute(gemm1_kernel, cudaFuncAttributeMaxDynamicSharedMemorySize, 2 * G1_STGW * 4);
    cudaFuncSetAttribute(gemm2_kernel, cudaFuncAttributeMaxDynamicSharedMemorySize, 2 * G2_STGW * 4);

    precompute_kernel<<<1, P>>>(Lam, ls);
    pack_sig_kernel<<<(L * 128) / 256, 256>>>(sig);
    pack_BH_kernel<<<64, 256>>>(Bt);
    pack_CH_kernel<<<64, 256>>>(Ct);
    gemm1_kernel<<<dim3(8, L / 128), 256, 2 * G1_STGW * 4>>>();
    scan_kernel<<<P, 512>>>();
    gemm2_kernel<<<dim3(4, L / 128), 256, 2 * G2_STGW * 4>>>(sig, Dv, y);
}